// round 15
// baseline (speedup 1.0000x reference)
#include <cuda_runtime.h>
#include <cstdint>

// ---------------------------------------------------------------------------
// Problem constants
// ---------------------------------------------------------------------------
#define LSEQ   4096
#define DM     192
#define DI     384
#define DS     16
#define DTR    12
#define NSEQ   8
#define NTOK   8192           // B * L
#define NROWS  32768          // NSEQ * L
#define CH_T   64             // chunk length
#define CH_G   64             // number of chunks

typedef unsigned long long ull;

// packed f32x2 helpers (sm_103a FFMA2 path)
__device__ __forceinline__ ull pk2(float lo, float hi) {
    ull r; asm("mov.b64 %0,{%1,%2};" : "=l"(r) : "f"(lo), "f"(hi)); return r;
}
__device__ __forceinline__ void upk(ull v, float& lo, float& hi) {
    asm("mov.b64 {%0,%1},%2;" : "=f"(lo), "=f"(hi) : "l"(v));
}
__device__ __forceinline__ ull fma2(ull a, ull b, ull c) {
    ull d; asm("fma.rn.f32x2 %0,%1,%2,%3;" : "=l"(d) : "l"(a), "l"(b), "l"(c)); return d;
}
__device__ __forceinline__ ull mul2(ull a, ull b) {
    ull d; asm("mul.rn.f32x2 %0,%1,%2;" : "=l"(d) : "l"(a), "l"(b)); return d;
}

// ---------------------------------------------------------------------------
// Scratch
// ---------------------------------------------------------------------------
__device__ float  g_P  [(size_t)NTOK  * 768];   // x @ in_proj_w
__device__ float  g_xcs[(size_t)NROWS * DI];    // silu(conv)
__device__ float  g_dbc[(size_t)NROWS * 44];    // xcs @ x_proj_w
__device__ float  g_hend[(size_t)NSEQ * CH_G * DS * DI];
__device__ float  g_h0  [(size_t)NSEQ * CH_G * DS * DI];
__device__ float  g_E  [(size_t)NSEQ * CH_G * DI];
__device__ float  g_y  [(size_t)NROWS * DI];    // y, stored UN-permuted
__device__ float  g_O1 [(size_t)NTOK  * DM];
__device__ float  g_N1 [(size_t)NTOK  * DM];

__device__ __forceinline__ int gmap(int dir, int t) {
    int p = t >> 6, q = t & 63;
    switch (dir) {
        case 0:  return t;
        case 1:  return ((63 - q) << 6) + p;
        case 2:  return ((63 - p) << 6) + (63 - q);
        default: return (q << 6) + (63 - p);
    }
}

// ---------------------------------------------------------------------------
// FP32 GEMM with packed f32x2 FMA: C[M,N] = A[M,K] @ W[K,N] (+resid+bias)
// Tile 128x64, BK=16, 128 threads, 8x8 microtile, register-prefetch pipeline.
// FUSEA: A is synthesized on the fly as (sum of 4 y dirs) * silu(z) (K==DI).
// ---------------------------------------------------------------------------
template<bool NG, bool RESID, bool FUSEA>
__global__ __launch_bounds__(128, 4)
void gemm_f2(const float* __restrict__ A, const float* __restrict__ W,
             float* __restrict__ C, int M, int N, int K,
             const float* __restrict__ resid, const float* __restrict__ bias)
{
    __shared__ __align__(16) float As[16][132];
    __shared__ __align__(16) float Bs[16][64];

    const int tid = threadIdx.x;
    const int tm = tid >> 3, tn = tid & 7;
    const int m0 = blockIdx.y * 128, n0 = blockIdx.x * 64;

    float4 rA[4], rB[2];

    auto loadA = [&](int k0) {
#pragma unroll
        for (int e = 0; e < 4; e++) {
            int l = e * 128 + tid; int r = l >> 2, kv = l & 3;
            if (FUSEA) {
                int row = m0 + r;
                int b = row >> 12, to = row & 4095;
                size_t co = (size_t)k0 + kv * 4;
                const float4 y0 = *reinterpret_cast<const float4*>(&g_y[((size_t)((0 + b) * LSEQ + to)) * DI + co]);
                const float4 y1 = *reinterpret_cast<const float4*>(&g_y[((size_t)((2 + b) * LSEQ + to)) * DI + co]);
                const float4 y2 = *reinterpret_cast<const float4*>(&g_y[((size_t)((4 + b) * LSEQ + to)) * DI + co]);
                const float4 y3 = *reinterpret_cast<const float4*>(&g_y[((size_t)((6 + b) * LSEQ + to)) * DI + co]);
                const float4 zz = *reinterpret_cast<const float4*>(&g_P[((size_t)(b * LSEQ + to)) * 768 + DI + co]);
                float4 v;
                v.x = (y0.x + y1.x + y2.x + y3.x) * (zz.x / (1.f + __expf(-zz.x)));
                v.y = (y0.y + y1.y + y2.y + y3.y) * (zz.y / (1.f + __expf(-zz.y)));
                v.z = (y0.z + y1.z + y2.z + y3.z) * (zz.z / (1.f + __expf(-zz.z)));
                v.w = (y0.w + y1.w + y2.w + y3.w) * (zz.w / (1.f + __expf(-zz.w)));
                rA[e] = v;
            } else {
                rA[e] = *reinterpret_cast<const float4*>(&A[(size_t)(m0 + r) * K + k0 + kv * 4]);
            }
        }
    };
    auto loadB = [&](int k0) {
#pragma unroll
        for (int e = 0; e < 2; e++) {
            int l = e * 128 + tid; int kk = l >> 4, c4 = l & 15;
            float4 w = make_float4(0.f, 0.f, 0.f, 0.f);
            if (!NG || (n0 + c4 * 4) < N)
                w = *reinterpret_cast<const float4*>(&W[(size_t)(k0 + kk) * N + n0 + c4 * 4]);
            rB[e] = w;
        }
    };
    auto stA = [&]() {
#pragma unroll
        for (int e = 0; e < 4; e++) {
            int l = e * 128 + tid; int r = l >> 2, kv = l & 3;
            As[kv * 4 + 0][r] = rA[e].x; As[kv * 4 + 1][r] = rA[e].y;
            As[kv * 4 + 2][r] = rA[e].z; As[kv * 4 + 3][r] = rA[e].w;
        }
    };
    auto stB = [&]() {
#pragma unroll
        for (int e = 0; e < 2; e++) {
            int l = e * 128 + tid; int kk = l >> 4, c4 = l & 15;
            *reinterpret_cast<float4*>(&Bs[kk][c4 * 4]) = rB[e];
        }
    };

    ull acc[8][4];
#pragma unroll
    for (int i = 0; i < 8; i++)
#pragma unroll
        for (int j = 0; j < 4; j++) acc[i][j] = 0ull;

    loadA(0); loadB(0);
    const int KT = K / 16;
    for (int kt = 0; kt < KT; kt++) {
        stA(); stB();
        __syncthreads();
        if (kt + 1 < KT) { loadA((kt + 1) * 16); loadB((kt + 1) * 16); }
#pragma unroll
        for (int kk = 0; kk < 16; kk++) {
            float4 a0 = *reinterpret_cast<const float4*>(&As[kk][tm * 8]);
            float4 a1 = *reinterpret_cast<const float4*>(&As[kk][tm * 8 + 4]);
            ull b[4];
#pragma unroll
            for (int j = 0; j < 4; j++)
                b[j] = *reinterpret_cast<const ull*>(&Bs[kk][tn * 8 + 2 * j]);
            float av[8] = {a0.x, a0.y, a0.z, a0.w, a1.x, a1.y, a1.z, a1.w};
#pragma unroll
            for (int i = 0; i < 8; i++) {
                ull ap = pk2(av[i], av[i]);
#pragma unroll
                for (int j = 0; j < 4; j++)
                    acc[i][j] = fma2(ap, b[j], acc[i][j]);
            }
        }
        __syncthreads();
    }

#pragma unroll
    for (int i = 0; i < 8; i++) {
        int r = m0 + tm * 8 + i;
#pragma unroll
        for (int j = 0; j < 4; j++) {
            int c = n0 + tn * 8 + 2 * j;
            if (NG && c >= N) continue;
            float lo, hi; upk(acc[i][j], lo, hi);
            size_t o = (size_t)r * N + c;
            if (RESID) { lo += resid[o] + bias[c]; hi += resid[o + 1] + bias[c + 1]; }
            float2 v = make_float2(lo, hi);
            *reinterpret_cast<float2*>(&C[o]) = v;
        }
    }
}

// ---------------------------------------------------------------------------
// Causal depthwise conv1d (4 taps) + SiLU: 8 timesteps/block, sliding window.
// ---------------------------------------------------------------------------
__global__ __launch_bounds__(384)
void conv_kernel(const float* __restrict__ conv_w, const float* __restrict__ conv_b)
{
    const int t0 = blockIdx.x * 8, n = blockIdx.y, d = threadIdx.x;
    const int dir = n >> 1, b = n & 1;
    const float w0 = conv_w[d * 4 + 0], w1 = conv_w[d * 4 + 1];
    const float w2 = conv_w[d * 4 + 2], w3 = conv_w[d * 4 + 3];
    const float bias = conv_b[d];

    float win0 = 0.f, win1 = 0.f, win2 = 0.f;
    if (t0 - 3 >= 0) win0 = g_P[((size_t)(b * LSEQ + gmap(dir, t0 - 3))) * 768 + d];
    if (t0 - 2 >= 0) win1 = g_P[((size_t)(b * LSEQ + gmap(dir, t0 - 2))) * 768 + d];
    if (t0 - 1 >= 0) win2 = g_P[((size_t)(b * LSEQ + gmap(dir, t0 - 1))) * 768 + d];

#pragma unroll
    for (int i = 0; i < 8; i++) {
        int t = t0 + i;
        float cur = g_P[((size_t)(b * LSEQ + gmap(dir, t))) * 768 + d];
        float acc = bias;
        acc = fmaf(w0, win0, acc);
        acc = fmaf(w1, win1, acc);
        acc = fmaf(w2, win2, acc);
        acc = fmaf(w3, cur,  acc);
        float s = acc / (1.f + __expf(-acc));
        g_xcs[((size_t)(n * LSEQ + t)) * DI + d] = s;
        win0 = win1; win1 = win2; win2 = cur;
    }
}

// Fast-path check: -A[d,s] == exp(A_log[d,s]) == s+1 for this problem.
__device__ __forceinline__ bool ladder_ok(const float* __restrict__ A_log, int d)
{
    bool ok = true;
#pragma unroll
    for (int s = 0; s < DS; s++) {
        float r = __expf(A_log[d * DS + s]);
        ok = ok && (fabsf(r - (float)(s + 1)) < 1e-3f);
    }
    return ok;
}

// Fused dt (R5 body): a = bias + lr·Wc -> e1 = 1/(1+e^a), dt = log(1+e^a)
__device__ __forceinline__ void dt_eval(const float* __restrict__ lr_t,
                                        const float* __restrict__ Wc, float bias,
                                        float& e1, float& dt)
{
    float a = bias;
#pragma unroll
    for (int k = 0; k < DTR; k++) a = fmaf(lr_t[k], Wc[k], a);
    float ea = __expf(a);
    float op = 1.f + ea;
    e1 = __fdividef(1.f, op);
    dt = __logf(op);
}

// ---------------------------------------------------------------------------
// S1: within-chunk recurrence (h0=0) -> h_end + decay product E.
// R5-measured-best body: serial dt dot, serial ap ladder, no prefetch.
// ---------------------------------------------------------------------------
__global__ __launch_bounds__(384)
void scan1_kernel(const float* __restrict__ A_log,
                  const float* __restrict__ dt_proj_w, const float* __restrict__ dt_proj_b)
{
    const int g = blockIdx.x, n = blockIdx.y, d = threadIdx.x;
    __shared__ __align__(16) float Bs[CH_T][DS];
    __shared__ float lr[CH_T][DTR];
    const int base = n * LSEQ + g * CH_T;
    for (int i = threadIdx.x; i < CH_T * DS; i += 384) {
        int t = i >> 4, s = i & 15;
        Bs[t][s] = g_dbc[(size_t)(base + t) * 44 + DTR + s];
    }
    for (int i = threadIdx.x; i < CH_T * DTR; i += 384)
        lr[i / DTR][i % DTR] = g_dbc[(size_t)(base + i / DTR) * 44 + (i % DTR)];

    float Wc[DTR];
#pragma unroll
    for (int k = 0; k < DTR; k++) Wc[k] = dt_proj_w[k * DI + d];
    const float bias = dt_proj_b[d];
    __syncthreads();

    const bool fast = ladder_ok(A_log, d);
    float E = 1.f;
    const int cg = n * CH_G + g;

    if (fast) {
        ull h[8];
#pragma unroll
        for (int j = 0; j < 8; j++) h[j] = 0ull;
        for (int t = 0; t < CH_T; t++) {
            float e, dt;
            dt_eval(lr[t], Wc, bias, e, dt);
            float u = dt * g_xcs[(size_t)(base + t) * DI + d];
            E *= e;
            float e2 = e * e;
            ull e2p = pk2(e2, e2);
            ull up  = pk2(u, u);
            ull ap  = pk2(e, e2);
#pragma unroll
            for (int j = 0; j < 8; j++) {
                ull Bp = *reinterpret_cast<const ull*>(&Bs[t][2 * j]);
                h[j] = fma2(h[j], ap, mul2(up, Bp));
                if (j < 7) ap = mul2(ap, e2p);
            }
        }
#pragma unroll
        for (int j = 0; j < 8; j++) {
            float lo, hi; upk(h[j], lo, hi);
            g_hend[((size_t)(cg * DS + 2 * j))     * DI + d] = lo;
            g_hend[((size_t)(cg * DS + 2 * j + 1)) * DI + d] = hi;
        }
    } else {
        float h[DS];
#pragma unroll
        for (int s = 0; s < DS; s++) h[s] = 0.f;
        for (int t = 0; t < CH_T; t++) {
            float e, dtv;
            dt_eval(lr[t], Wc, bias, e, dtv);
            float u = dtv * g_xcs[(size_t)(base + t) * DI + d];
            E *= e;
#pragma unroll
            for (int s = 0; s < DS; s++) {
                float a = __expf(-dtv * __expf(A_log[d * DS + s]));
                h[s] = fmaf(h[s], a, u * Bs[t][s]);
            }
        }
#pragma unroll
        for (int s = 0; s < DS; s++)
            g_hend[((size_t)(cg * DS + s)) * DI + d] = h[s];
    }
    g_E[(size_t)cg * DI + d] = E;
}

// ---------------------------------------------------------------------------
// S2: serial scan over 64 chunk summaries per channel -> per-chunk h0
// ---------------------------------------------------------------------------
__global__ __launch_bounds__(384)
void scan2_kernel(const float* __restrict__ A_log)
{
    const int s = blockIdx.x, n = blockIdx.y, d = threadIdx.x;
    float r = __expf(A_log[d * DS + s]);
    const bool fast = fabsf(r - (float)(s + 1)) < 1e-3f;
    float h = 0.f;
    for (int g = 0; g < CH_G; g++) {
        int cg = n * CH_G + g;
        float E = g_E[(size_t)cg * DI + d];
        float a;
        if (fast) {
            a = 1.f; float p = E; int m = s + 1;
            while (m) { if (m & 1) a *= p; p *= p; m >>= 1; }
        } else {
            a = __powf(E, r);
        }
        size_t idx = ((size_t)(cg * DS + s)) * DI + d;
        g_h0[idx] = h;
        h = fmaf(a, h, g_hend[idx]);
    }
}

// ---------------------------------------------------------------------------
// S3: replay chunk from true h0, emit y (UN-permuted by gmap). R5 body.
// ---------------------------------------------------------------------------
__global__ __launch_bounds__(384)
void scan3_kernel(const float* __restrict__ A_log, const float* __restrict__ Dv,
                  const float* __restrict__ dt_proj_w, const float* __restrict__ dt_proj_b)
{
    const int g = blockIdx.x, n = blockIdx.y, d = threadIdx.x;
    const int dir = n >> 1;
    __shared__ __align__(16) float Bs[CH_T][DS];
    __shared__ __align__(16) float Cs[CH_T][DS];
    __shared__ float lr[CH_T][DTR];
    const int base = n * LSEQ + g * CH_T;
    for (int i = threadIdx.x; i < CH_T * DS; i += 384) {
        int t = i >> 4, s = i & 15;
        size_t ro = (size_t)(base + t) * 44;
        Bs[t][s] = g_dbc[ro + DTR + s];
        Cs[t][s] = g_dbc[ro + DTR + DS + s];
    }
    for (int i = threadIdx.x; i < CH_T * DTR; i += 384)
        lr[i / DTR][i % DTR] = g_dbc[(size_t)(base + i / DTR) * 44 + (i % DTR)];

    float Wc[DTR];
#pragma unroll
    for (int k = 0; k < DTR; k++) Wc[k] = dt_proj_w[k * DI + d];
    const float bias = dt_proj_b[d];
    __syncthreads();

    const bool fast = ladder_ok(A_log, d);
    const int cg = n * CH_G + g;
    const float Dd = Dv[d];

    if (fast) {
        ull h[8];
#pragma unroll
        for (int j = 0; j < 8; j++)
            h[j] = pk2(g_h0[((size_t)(cg * DS + 2 * j))     * DI + d],
                       g_h0[((size_t)(cg * DS + 2 * j + 1)) * DI + d]);
        for (int t = 0; t < CH_T; t++) {
            size_t idx = (size_t)(base + t) * DI + d;
            float e, dt;
            dt_eval(lr[t], Wc, bias, e, dt);
            float xc = g_xcs[idx];
            float u = dt * xc;
            float e2 = e * e;
            ull e2p = pk2(e2, e2);
            ull up  = pk2(u, u);
            ull ap  = pk2(e, e2);
            ull y2  = 0ull;
#pragma unroll
            for (int j = 0; j < 8; j++) {
                ull Bp = *reinterpret_cast<const ull*>(&Bs[t][2 * j]);
                ull Cp = *reinterpret_cast<const ull*>(&Cs[t][2 * j]);
                h[j] = fma2(h[j], ap, mul2(up, Bp));
                y2   = fma2(h[j], Cp, y2);
                if (j < 7) ap = mul2(ap, e2p);
            }
            float ylo, yhi; upk(y2, ylo, yhi);
            float y = ylo + yhi;
            y = fmaf(xc, Dd, y);
            int u_tok = gmap(dir, g * CH_T + t);
            g_y[((size_t)(n * LSEQ + u_tok)) * DI + d] = y;
        }
    } else {
        float h[DS];
#pragma unroll
        for (int s = 0; s < DS; s++)
            h[s] = g_h0[((size_t)(cg * DS + s)) * DI + d];
        for (int t = 0; t < CH_T; t++) {
            size_t idx = (size_t)(base + t) * DI + d;
            float e, dtv;
            dt_eval(lr[t], Wc, bias, e, dtv);
            float xc = g_xcs[idx];
            float u = dtv * xc;
            float y = 0.f;
#pragma unroll
            for (int s = 0; s < DS; s++) {
                float a = __expf(-dtv * __expf(A_log[d * DS + s]));
                h[s] = fmaf(h[s], a, u * Bs[t][s]);
                y = fmaf(h[s], Cs[t][s], y);
            }
            y = fmaf(xc, Dd, y);
            int u_tok = gmap(dir, g * CH_T + t);
            g_y[((size_t)(n * LSEQ + u_tok)) * DI + d] = y;
        }
    }
}

// ---------------------------------------------------------------------------
// LayerNorm over 192 channels
// ---------------------------------------------------------------------------
__global__ __launch_bounds__(192)
void ln_kernel(const float* __restrict__ lg, const float* __restrict__ lb)
{
    const int u = blockIdx.x, j = threadIdx.x;
    float v = g_O1[(size_t)u * DM + j];
    __shared__ float rs[6], rq[6], stats[2];
    float s1 = v, s2 = v * v;
#pragma unroll
    for (int o = 16; o > 0; o >>= 1) {
        s1 += __shfl_down_sync(0xffffffffu, s1, o);
        s2 += __shfl_down_sync(0xffffffffu, s2, o);
    }
    if ((j & 31) == 0) { rs[j >> 5] = s1; rq[j >> 5] = s2; }
    __syncthreads();
    if (j == 0) {
        float a = 0.f, q = 0.f;
        for (int i = 0; i < 6; i++) { a += rs[i]; q += rq[i]; }
        float mu = a * (1.f / DM);
        float var = q * (1.f / DM) - mu * mu;
        stats[0] = mu; stats[1] = rsqrtf(var + 1e-5f);
    }
    __syncthreads();
    g_N1[(size_t)u * DM + j] = (v - stats[0]) * stats[1] * lg[j] + lb[j];
}

// ---------------------------------------------------------------------------
// Launch
// ---------------------------------------------------------------------------
extern "C" void kernel_launch(void* const* d_in, const int* in_sizes, int n_in,
                              void* d_out, int out_size)
{
    const float* x           = (const float*)d_in[0];
    const float* in_proj_w   = (const float*)d_in[1];
    const float* conv_w      = (const float*)d_in[2];
    const float* conv_b      = (const float*)d_in[3];
    const float* x_proj_w    = (const float*)d_in[4];
    const float* dt_proj_w   = (const float*)d_in[5];
    const float* dt_proj_b   = (const float*)d_in[6];
    const float* A_log       = (const float*)d_in[7];
    const float* Dv          = (const float*)d_in[8];
    const float* mamba_out_w = (const float*)d_in[9];
    const float* ln_g        = (const float*)d_in[10];
    const float* ln_b        = (const float*)d_in[11];
    const float* blk_w       = (const float*)d_in[12];
    const float* blk_b       = (const float*)d_in[13];
    float* out = (float*)d_out;

    float *P, *xcs, *dbc, *O1, *N1;
    cudaGetSymbolAddress((void**)&P,   g_P);
    cudaGetSymbolAddress((void**)&xcs, g_xcs);
    cudaGetSymbolAddress((void**)&dbc, g_dbc);
    cudaGetSymbolAddress((void**)&O1,  g_O1);
    cudaGetSymbolAddress((void**)&N1,  g_N1);

    // 1) P = x @ in_proj_w              [8192,192]x[192,768]
    gemm_f2<false, false, false><<<dim3(12, 64), 128>>>(x, in_proj_w, P,
                                                        NTOK, 768, DM, nullptr, nullptr);
    // 2) depthwise conv + SiLU (8 t/block, sliding window)
    conv_kernel<<<dim3(LSEQ / 8, NSEQ), 384>>>(conv_w, conv_b);
    // 3) dbc = xcs @ x_proj_w           [32768,384]x[384,44]
    gemm_f2<true, false, false><<<dim3(1, 256), 128>>>(xcs, x_proj_w, dbc,
                                                       NROWS, 44, DI, nullptr, nullptr);
    // 4-6) chunked selective scan (R5-measured-best bodies)
    scan1_kernel<<<dim3(CH_G, NSEQ), 384>>>(A_log, dt_proj_w, dt_proj_b);
    scan2_kernel<<<dim3(DS, NSEQ), 384>>>(A_log);
    scan3_kernel<<<dim3(CH_G, NSEQ), 384>>>(A_log, Dv, dt_proj_w, dt_proj_b);
    // 7) O1 = [(sum_dir y) * silu(z)] @ mamba_out_w  (gather fused into A load)
    gemm_f2<false, false, true><<<dim3(3, 64), 128>>>(nullptr, mamba_out_w, O1,
                                                      NTOK, DM, DI, nullptr, nullptr);
    // 8) LayerNorm
    ln_kernel<<<NTOK, DM>>>(ln_g, ln_b);
    // 9) out = x + N1 @ blk_w + blk_b
    gemm_f2<false, true, false><<<dim3(3, 64), 128>>>(N1, blk_w, out,
                                                      NTOK, DM, DM, x, blk_b);
    (void)in_sizes; (void)n_in; (void)out_size;
}

// round 16
// speedup vs baseline: 1.1343x; 1.1343x over previous
#include <cuda_runtime.h>
#include <cstdint>

// ---------------------------------------------------------------------------
// Problem constants
// ---------------------------------------------------------------------------
#define LSEQ   4096
#define DM     192
#define DI     384
#define DS     16
#define DTR    12
#define NSEQ   8
#define NTOK   8192           // B * L
#define NROWS  32768          // NSEQ * L
#define CH_T   64             // chunk length
#define CH_G   64             // number of chunks

typedef unsigned long long ull;

// packed f32x2 helpers (sm_103a FFMA2 path)
__device__ __forceinline__ ull pk2(float lo, float hi) {
    ull r; asm("mov.b64 %0,{%1,%2};" : "=l"(r) : "f"(lo), "f"(hi)); return r;
}
__device__ __forceinline__ void upk(ull v, float& lo, float& hi) {
    asm("mov.b64 {%0,%1},%2;" : "=f"(lo), "=f"(hi) : "l"(v));
}
__device__ __forceinline__ ull fma2(ull a, ull b, ull c) {
    ull d; asm("fma.rn.f32x2 %0,%1,%2,%3;" : "=l"(d) : "l"(a), "l"(b), "l"(c)); return d;
}
__device__ __forceinline__ ull mul2(ull a, ull b) {
    ull d; asm("mul.rn.f32x2 %0,%1,%2;" : "=l"(d) : "l"(a), "l"(b)); return d;
}

// ---------------------------------------------------------------------------
// Scratch
// ---------------------------------------------------------------------------
__device__ float  g_P  [(size_t)NTOK  * 768];   // x @ in_proj_w
__device__ float  g_xcs[(size_t)NROWS * DI];    // silu(conv)
__device__ float  g_dbc[(size_t)NROWS * 44];    // xcs @ x_proj_w
__device__ float  g_hend[(size_t)NSEQ * CH_G * DS * DI];
__device__ float  g_h0  [(size_t)NSEQ * CH_G * DS * DI];
__device__ float  g_E  [(size_t)NSEQ * CH_G * DI];
__device__ float  g_y  [(size_t)NROWS * DI];    // y, stored UN-permuted
__device__ float  g_G  [(size_t)NTOK  * DI];    // (sum_dir y) * silu(z)
__device__ float  g_O1 [(size_t)NTOK  * DM];
__device__ float  g_N1 [(size_t)NTOK  * DM];

__device__ __forceinline__ int gmap(int dir, int t) {
    int p = t >> 6, q = t & 63;
    switch (dir) {
        case 0:  return t;
        case 1:  return ((63 - q) << 6) + p;
        case 2:  return ((63 - p) << 6) + (63 - q);
        default: return (q << 6) + (63 - p);
    }
}

// ---------------------------------------------------------------------------
// FP32 GEMM with packed f32x2 FMA: C[M,N] = A[M,K] @ W[K,N] (+resid+bias)
// Tile 128x64, BK=16, 128 threads, 8x8 microtile, register-prefetch pipeline.
// ---------------------------------------------------------------------------
template<bool NG, bool RESID>
__global__ __launch_bounds__(128, 4)
void gemm_f2(const float* __restrict__ A, const float* __restrict__ W,
             float* __restrict__ C, int M, int N, int K,
             const float* __restrict__ resid, const float* __restrict__ bias)
{
    __shared__ __align__(16) float As[16][132];
    __shared__ __align__(16) float Bs[16][64];

    const int tid = threadIdx.x;
    const int tm = tid >> 3, tn = tid & 7;
    const int m0 = blockIdx.y * 128, n0 = blockIdx.x * 64;

    float4 rA[4], rB[2];

    auto loadA = [&](int k0) {
#pragma unroll
        for (int e = 0; e < 4; e++) {
            int l = e * 128 + tid; int r = l >> 2, kv = l & 3;
            rA[e] = *reinterpret_cast<const float4*>(&A[(size_t)(m0 + r) * K + k0 + kv * 4]);
        }
    };
    auto loadB = [&](int k0) {
#pragma unroll
        for (int e = 0; e < 2; e++) {
            int l = e * 128 + tid; int kk = l >> 4, c4 = l & 15;
            float4 w = make_float4(0.f, 0.f, 0.f, 0.f);
            if (!NG || (n0 + c4 * 4) < N)
                w = *reinterpret_cast<const float4*>(&W[(size_t)(k0 + kk) * N + n0 + c4 * 4]);
            rB[e] = w;
        }
    };
    auto stA = [&]() {
#pragma unroll
        for (int e = 0; e < 4; e++) {
            int l = e * 128 + tid; int r = l >> 2, kv = l & 3;
            As[kv * 4 + 0][r] = rA[e].x; As[kv * 4 + 1][r] = rA[e].y;
            As[kv * 4 + 2][r] = rA[e].z; As[kv * 4 + 3][r] = rA[e].w;
        }
    };
    auto stB = [&]() {
#pragma unroll
        for (int e = 0; e < 2; e++) {
            int l = e * 128 + tid; int kk = l >> 4, c4 = l & 15;
            *reinterpret_cast<float4*>(&Bs[kk][c4 * 4]) = rB[e];
        }
    };

    ull acc[8][4];
#pragma unroll
    for (int i = 0; i < 8; i++)
#pragma unroll
        for (int j = 0; j < 4; j++) acc[i][j] = 0ull;

    loadA(0); loadB(0);
    const int KT = K / 16;
    for (int kt = 0; kt < KT; kt++) {
        stA(); stB();
        __syncthreads();
        if (kt + 1 < KT) { loadA((kt + 1) * 16); loadB((kt + 1) * 16); }
#pragma unroll
        for (int kk = 0; kk < 16; kk++) {
            float4 a0 = *reinterpret_cast<const float4*>(&As[kk][tm * 8]);
            float4 a1 = *reinterpret_cast<const float4*>(&As[kk][tm * 8 + 4]);
            ull b[4];
#pragma unroll
            for (int j = 0; j < 4; j++)
                b[j] = *reinterpret_cast<const ull*>(&Bs[kk][tn * 8 + 2 * j]);
            float av[8] = {a0.x, a0.y, a0.z, a0.w, a1.x, a1.y, a1.z, a1.w};
#pragma unroll
            for (int i = 0; i < 8; i++) {
                ull ap = pk2(av[i], av[i]);
#pragma unroll
                for (int j = 0; j < 4; j++)
                    acc[i][j] = fma2(ap, b[j], acc[i][j]);
            }
        }
        __syncthreads();
    }

#pragma unroll
    for (int i = 0; i < 8; i++) {
        int r = m0 + tm * 8 + i;
#pragma unroll
        for (int j = 0; j < 4; j++) {
            int c = n0 + tn * 8 + 2 * j;
            if (NG && c >= N) continue;
            float lo, hi; upk(acc[i][j], lo, hi);
            size_t o = (size_t)r * N + c;
            if (RESID) { lo += resid[o] + bias[c]; hi += resid[o + 1] + bias[c + 1]; }
            float2 v = make_float2(lo, hi);
            *reinterpret_cast<float2*>(&C[o]) = v;
        }
    }
}

// ---------------------------------------------------------------------------
// Causal depthwise conv1d (4 taps) + SiLU: 8 timesteps/block, sliding window.
// ---------------------------------------------------------------------------
__global__ __launch_bounds__(384)
void conv_kernel(const float* __restrict__ conv_w, const float* __restrict__ conv_b)
{
    const int t0 = blockIdx.x * 8, n = blockIdx.y, d = threadIdx.x;
    const int dir = n >> 1, b = n & 1;
    const float w0 = conv_w[d * 4 + 0], w1 = conv_w[d * 4 + 1];
    const float w2 = conv_w[d * 4 + 2], w3 = conv_w[d * 4 + 3];
    const float bias = conv_b[d];

    float win0 = 0.f, win1 = 0.f, win2 = 0.f;
    if (t0 - 3 >= 0) win0 = g_P[((size_t)(b * LSEQ + gmap(dir, t0 - 3))) * 768 + d];
    if (t0 - 2 >= 0) win1 = g_P[((size_t)(b * LSEQ + gmap(dir, t0 - 2))) * 768 + d];
    if (t0 - 1 >= 0) win2 = g_P[((size_t)(b * LSEQ + gmap(dir, t0 - 1))) * 768 + d];

#pragma unroll
    for (int i = 0; i < 8; i++) {
        int t = t0 + i;
        float cur = g_P[((size_t)(b * LSEQ + gmap(dir, t))) * 768 + d];
        float acc = bias;
        acc = fmaf(w0, win0, acc);
        acc = fmaf(w1, win1, acc);
        acc = fmaf(w2, win2, acc);
        acc = fmaf(w3, cur,  acc);
        float s = acc / (1.f + __expf(-acc));
        g_xcs[((size_t)(n * LSEQ + t)) * DI + d] = s;
        win0 = win1; win1 = win2; win2 = cur;
    }
}

// Fast-path check: -A[d,s] == exp(A_log[d,s]) == s+1 for this problem.
__device__ __forceinline__ bool ladder_ok(const float* __restrict__ A_log, int d)
{
    bool ok = true;
#pragma unroll
    for (int s = 0; s < DS; s++) {
        float r = __expf(A_log[d * DS + s]);
        ok = ok && (fabsf(r - (float)(s + 1)) < 1e-3f);
    }
    return ok;
}

// Fused dt (R5 body): a = bias + lr·Wc -> e1 = 1/(1+e^a), dt = log(1+e^a)
__device__ __forceinline__ void dt_eval(const float* __restrict__ lr_t,
                                        const float* __restrict__ Wc, float bias,
                                        float& e1, float& dt)
{
    float a = bias;
#pragma unroll
    for (int k = 0; k < DTR; k++) a = fmaf(lr_t[k], Wc[k], a);
    float ea = __expf(a);
    float op = 1.f + ea;
    e1 = __fdividef(1.f, op);
    dt = __logf(op);
}

// ---------------------------------------------------------------------------
// S1: within-chunk recurrence (h0=0) -> h_end + decay product E.
// R5-measured-best body (56.7us confirmed in R14).
// ---------------------------------------------------------------------------
__global__ __launch_bounds__(384)
void scan1_kernel(const float* __restrict__ A_log,
                  const float* __restrict__ dt_proj_w, const float* __restrict__ dt_proj_b)
{
    const int g = blockIdx.x, n = blockIdx.y, d = threadIdx.x;
    __shared__ __align__(16) float Bs[CH_T][DS];
    __shared__ float lr[CH_T][DTR];
    const int base = n * LSEQ + g * CH_T;
    for (int i = threadIdx.x; i < CH_T * DS; i += 384) {
        int t = i >> 4, s = i & 15;
        Bs[t][s] = g_dbc[(size_t)(base + t) * 44 + DTR + s];
    }
    for (int i = threadIdx.x; i < CH_T * DTR; i += 384)
        lr[i / DTR][i % DTR] = g_dbc[(size_t)(base + i / DTR) * 44 + (i % DTR)];

    float Wc[DTR];
#pragma unroll
    for (int k = 0; k < DTR; k++) Wc[k] = dt_proj_w[k * DI + d];
    const float bias = dt_proj_b[d];
    __syncthreads();

    const bool fast = ladder_ok(A_log, d);
    float E = 1.f;
    const int cg = n * CH_G + g;

    if (fast) {
        ull h[8];
#pragma unroll
        for (int j = 0; j < 8; j++) h[j] = 0ull;
        for (int t = 0; t < CH_T; t++) {
            float e, dt;
            dt_eval(lr[t], Wc, bias, e, dt);
            float u = dt * g_xcs[(size_t)(base + t) * DI + d];
            E *= e;
            float e2 = e * e;
            ull e2p = pk2(e2, e2);
            ull up  = pk2(u, u);
            ull ap  = pk2(e, e2);
#pragma unroll
            for (int j = 0; j < 8; j++) {
                ull Bp = *reinterpret_cast<const ull*>(&Bs[t][2 * j]);
                h[j] = fma2(h[j], ap, mul2(up, Bp));
                if (j < 7) ap = mul2(ap, e2p);
            }
        }
#pragma unroll
        for (int j = 0; j < 8; j++) {
            float lo, hi; upk(h[j], lo, hi);
            g_hend[((size_t)(cg * DS + 2 * j))     * DI + d] = lo;
            g_hend[((size_t)(cg * DS + 2 * j + 1)) * DI + d] = hi;
        }
    } else {
        float h[DS];
#pragma unroll
        for (int s = 0; s < DS; s++) h[s] = 0.f;
        for (int t = 0; t < CH_T; t++) {
            float e, dtv;
            dt_eval(lr[t], Wc, bias, e, dtv);
            float u = dtv * g_xcs[(size_t)(base + t) * DI + d];
            E *= e;
#pragma unroll
            for (int s = 0; s < DS; s++) {
                float a = __expf(-dtv * __expf(A_log[d * DS + s]));
                h[s] = fmaf(h[s], a, u * Bs[t][s]);
            }
        }
#pragma unroll
        for (int s = 0; s < DS; s++)
            g_hend[((size_t)(cg * DS + s)) * DI + d] = h[s];
    }
    g_E[(size_t)cg * DI + d] = E;
}

// ---------------------------------------------------------------------------
// S2: serial scan over 64 chunk summaries per channel -> per-chunk h0
// ---------------------------------------------------------------------------
__global__ __launch_bounds__(384)
void scan2_kernel(const float* __restrict__ A_log)
{
    const int s = blockIdx.x, n = blockIdx.y, d = threadIdx.x;
    float r = __expf(A_log[d * DS + s]);
    const bool fast = fabsf(r - (float)(s + 1)) < 1e-3f;
    float h = 0.f;
    for (int g = 0; g < CH_G; g++) {
        int cg = n * CH_G + g;
        float E = g_E[(size_t)cg * DI + d];
        float a;
        if (fast) {
            a = 1.f; float p = E; int m = s + 1;
            while (m) { if (m & 1) a *= p; p *= p; m >>= 1; }
        } else {
            a = __powf(E, r);
        }
        size_t idx = ((size_t)(cg * DS + s)) * DI + d;
        g_h0[idx] = h;
        h = fmaf(a, h, g_hend[idx]);
    }
}

// ---------------------------------------------------------------------------
// S3: replay chunk from true h0, emit y (UN-permuted by gmap). R5 body.
// ---------------------------------------------------------------------------
__global__ __launch_bounds__(384)
void scan3_kernel(const float* __restrict__ A_log, const float* __restrict__ Dv,
                  const float* __restrict__ dt_proj_w, const float* __restrict__ dt_proj_b)
{
    const int g = blockIdx.x, n = blockIdx.y, d = threadIdx.x;
    const int dir = n >> 1;
    __shared__ __align__(16) float Bs[CH_T][DS];
    __shared__ __align__(16) float Cs[CH_T][DS];
    __shared__ float lr[CH_T][DTR];
    const int base = n * LSEQ + g * CH_T;
    for (int i = threadIdx.x; i < CH_T * DS; i += 384) {
        int t = i >> 4, s = i & 15;
        size_t ro = (size_t)(base + t) * 44;
        Bs[t][s] = g_dbc[ro + DTR + s];
        Cs[t][s] = g_dbc[ro + DTR + DS + s];
    }
    for (int i = threadIdx.x; i < CH_T * DTR; i += 384)
        lr[i / DTR][i % DTR] = g_dbc[(size_t)(base + i / DTR) * 44 + (i % DTR)];

    float Wc[DTR];
#pragma unroll
    for (int k = 0; k < DTR; k++) Wc[k] = dt_proj_w[k * DI + d];
    const float bias = dt_proj_b[d];
    __syncthreads();

    const bool fast = ladder_ok(A_log, d);
    const int cg = n * CH_G + g;
    const float Dd = Dv[d];

    if (fast) {
        ull h[8];
#pragma unroll
        for (int j = 0; j < 8; j++)
            h[j] = pk2(g_h0[((size_t)(cg * DS + 2 * j))     * DI + d],
                       g_h0[((size_t)(cg * DS + 2 * j + 1)) * DI + d]);
        for (int t = 0; t < CH_T; t++) {
            size_t idx = (size_t)(base + t) * DI + d;
            float e, dt;
            dt_eval(lr[t], Wc, bias, e, dt);
            float xc = g_xcs[idx];
            float u = dt * xc;
            float e2 = e * e;
            ull e2p = pk2(e2, e2);
            ull up  = pk2(u, u);
            ull ap  = pk2(e, e2);
            ull y2  = 0ull;
#pragma unroll
            for (int j = 0; j < 8; j++) {
                ull Bp = *reinterpret_cast<const ull*>(&Bs[t][2 * j]);
                ull Cp = *reinterpret_cast<const ull*>(&Cs[t][2 * j]);
                h[j] = fma2(h[j], ap, mul2(up, Bp));
                y2   = fma2(h[j], Cp, y2);
                if (j < 7) ap = mul2(ap, e2p);
            }
            float ylo, yhi; upk(y2, ylo, yhi);
            float y = ylo + yhi;
            y = fmaf(xc, Dd, y);
            int u_tok = gmap(dir, g * CH_T + t);
            g_y[((size_t)(n * LSEQ + u_tok)) * DI + d] = y;
        }
    } else {
        float h[DS];
#pragma unroll
        for (int s = 0; s < DS; s++)
            h[s] = g_h0[((size_t)(cg * DS + s)) * DI + d];
        for (int t = 0; t < CH_T; t++) {
            size_t idx = (size_t)(base + t) * DI + d;
            float e, dtv;
            dt_eval(lr[t], Wc, bias, e, dtv);
            float xc = g_xcs[idx];
            float u = dtv * xc;
            float y = 0.f;
#pragma unroll
            for (int s = 0; s < DS; s++) {
                float a = __expf(-dtv * __expf(A_log[d * DS + s]));
                h[s] = fmaf(h[s], a, u * Bs[t][s]);
                y = fmaf(h[s], Cs[t][s], y);
            }
            y = fmaf(xc, Dd, y);
            int u_tok = gmap(dir, g * CH_T + t);
            g_y[((size_t)(n * LSEQ + u_tok)) * DI + d] = y;
        }
    }
}

// ---------------------------------------------------------------------------
// Sum the 4 (already un-permuted) directional y's, multiply by silu(z).
// Single pass over y — measured cheaper than fusing into the out GEMM (R14).
// ---------------------------------------------------------------------------
__global__ __launch_bounds__(384)
void gather_kernel()
{
    const int u = blockIdx.x, d = threadIdx.x;
    const int b = u >> 12, to = u & 4095;
    float ys = g_y[((size_t)((0 + b) * LSEQ + to)) * DI + d]
             + g_y[((size_t)((2 + b) * LSEQ + to)) * DI + d]
             + g_y[((size_t)((4 + b) * LSEQ + to)) * DI + d]
             + g_y[((size_t)((6 + b) * LSEQ + to)) * DI + d];
    float z  = g_P[((size_t)(b * LSEQ + to)) * 768 + DI + d];
    float sz = z / (1.f + __expf(-z));
    g_G[((size_t)u) * DI + d] = ys * sz;
}

// ---------------------------------------------------------------------------
// LayerNorm over 192 channels
// ---------------------------------------------------------------------------
__global__ __launch_bounds__(192)
void ln_kernel(const float* __restrict__ lg, const float* __restrict__ lb)
{
    const int u = blockIdx.x, j = threadIdx.x;
    float v = g_O1[(size_t)u * DM + j];
    __shared__ float rs[6], rq[6], stats[2];
    float s1 = v, s2 = v * v;
#pragma unroll
    for (int o = 16; o > 0; o >>= 1) {
        s1 += __shfl_down_sync(0xffffffffu, s1, o);
        s2 += __shfl_down_sync(0xffffffffu, s2, o);
    }
    if ((j & 31) == 0) { rs[j >> 5] = s1; rq[j >> 5] = s2; }
    __syncthreads();
    if (j == 0) {
        float a = 0.f, q = 0.f;
        for (int i = 0; i < 6; i++) { a += rs[i]; q += rq[i]; }
        float mu = a * (1.f / DM);
        float var = q * (1.f / DM) - mu * mu;
        stats[0] = mu; stats[1] = rsqrtf(var + 1e-5f);
    }
    __syncthreads();
    g_N1[(size_t)u * DM + j] = (v - stats[0]) * stats[1] * lg[j] + lb[j];
}

// ---------------------------------------------------------------------------
// Launch
// ---------------------------------------------------------------------------
extern "C" void kernel_launch(void* const* d_in, const int* in_sizes, int n_in,
                              void* d_out, int out_size)
{
    const float* x           = (const float*)d_in[0];
    const float* in_proj_w   = (const float*)d_in[1];
    const float* conv_w      = (const float*)d_in[2];
    const float* conv_b      = (const float*)d_in[3];
    const float* x_proj_w    = (const float*)d_in[4];
    const float* dt_proj_w   = (const float*)d_in[5];
    const float* dt_proj_b   = (const float*)d_in[6];
    const float* A_log       = (const float*)d_in[7];
    const float* Dv          = (const float*)d_in[8];
    const float* mamba_out_w = (const float*)d_in[9];
    const float* ln_g        = (const float*)d_in[10];
    const float* ln_b        = (const float*)d_in[11];
    const float* blk_w       = (const float*)d_in[12];
    const float* blk_b       = (const float*)d_in[13];
    float* out = (float*)d_out;

    float *P, *xcs, *dbc, *G, *O1, *N1;
    cudaGetSymbolAddress((void**)&P,   g_P);
    cudaGetSymbolAddress((void**)&xcs, g_xcs);
    cudaGetSymbolAddress((void**)&dbc, g_dbc);
    cudaGetSymbolAddress((void**)&G,   g_G);
    cudaGetSymbolAddress((void**)&O1,  g_O1);
    cudaGetSymbolAddress((void**)&N1,  g_N1);

    // 1) P = x @ in_proj_w              [8192,192]x[192,768]
    gemm_f2<false, false><<<dim3(12, 64), 128>>>(x, in_proj_w, P,
                                                 NTOK, 768, DM, nullptr, nullptr);
    // 2) depthwise conv + SiLU (8 t/block, sliding window)
    conv_kernel<<<dim3(LSEQ / 8, NSEQ), 384>>>(conv_w, conv_b);
    // 3) dbc = xcs @ x_proj_w           [32768,384]x[384,44]
    gemm_f2<true, false><<<dim3(1, 256), 128>>>(xcs, x_proj_w, dbc,
                                                NROWS, 44, DI, nullptr, nullptr);
    // 4-6) chunked selective scan (R5-measured-best bodies)
    scan1_kernel<<<dim3(CH_G, NSEQ), 384>>>(A_log, dt_proj_w, dt_proj_b);
    scan2_kernel<<<dim3(DS, NSEQ), 384>>>(A_log);
    scan3_kernel<<<dim3(CH_G, NSEQ), 384>>>(A_log, Dv, dt_proj_w, dt_proj_b);
    // 7) direction merge * silu(z)  (separate pass — measured better than FUSEA)
    gather_kernel<<<NTOK, 384>>>();
    // 8) O1 = G @ mamba_out_w           [8192,384]x[384,192]
    gemm_f2<false, false><<<dim3(3, 64), 128>>>(G, mamba_out_w, O1,
                                                NTOK, DM, DI, nullptr, nullptr);
    // 9) LayerNorm
    ln_kernel<<<NTOK, DM>>>(ln_g, ln_b);
    // 10) out = x + N1 @ blk_w + blk_b
    gemm_f2<false, true><<<dim3(3, 64), 128>>>(N1, blk_w, out,
                                               NTOK, DM, DM, x, blk_b);
    (void)in_sizes; (void)n_in; (void)out_size;
}

// round 17
// speedup vs baseline: 1.1635x; 1.0257x over previous
#include <cuda_runtime.h>
#include <cstdint>

// ---------------------------------------------------------------------------
// Problem constants
// ---------------------------------------------------------------------------
#define LSEQ   4096
#define DM     192
#define DI     384
#define DS     16
#define DTR    12
#define NSEQ   8
#define NTOK   8192           // B * L
#define NROWS  32768          // NSEQ * L
#define CH_T   64             // chunk length
#define CH_G   64             // number of chunks

typedef unsigned long long ull;

// packed f32x2 helpers (sm_103a FFMA2 path)
__device__ __forceinline__ ull pk2(float lo, float hi) {
    ull r; asm("mov.b64 %0,{%1,%2};" : "=l"(r) : "f"(lo), "f"(hi)); return r;
}
__device__ __forceinline__ void upk(ull v, float& lo, float& hi) {
    asm("mov.b64 {%0,%1},%2;" : "=f"(lo), "=f"(hi) : "l"(v));
}
__device__ __forceinline__ ull fma2(ull a, ull b, ull c) {
    ull d; asm("fma.rn.f32x2 %0,%1,%2,%3;" : "=l"(d) : "l"(a), "l"(b), "l"(c)); return d;
}
__device__ __forceinline__ ull mul2(ull a, ull b) {
    ull d; asm("mul.rn.f32x2 %0,%1,%2;" : "=l"(d) : "l"(a), "l"(b)); return d;
}

// ---------------------------------------------------------------------------
// Scratch
// ---------------------------------------------------------------------------
__device__ float  g_P  [(size_t)NTOK  * 768];   // x @ in_proj_w
__device__ float  g_xcs[(size_t)NROWS * DI];    // silu(conv)
__device__ float  g_dbc[(size_t)NROWS * 44];    // xcs @ x_proj_w
__device__ float  g_hend[(size_t)NSEQ * CH_G * DS * DI];
__device__ float  g_h0  [(size_t)NSEQ * CH_G * DS * DI];
__device__ float  g_E  [(size_t)NSEQ * CH_G * DI];
__device__ float  g_y  [(size_t)NROWS * DI];    // y, stored UN-permuted
__device__ float  g_G  [(size_t)NTOK  * DI];    // (sum_dir y) * silu(z)
__device__ float  g_O1 [(size_t)NTOK  * DM];
__device__ float  g_N1 [(size_t)NTOK  * DM];

__device__ __forceinline__ int gmap(int dir, int t) {
    int p = t >> 6, q = t & 63;
    switch (dir) {
        case 0:  return t;
        case 1:  return ((63 - q) << 6) + p;
        case 2:  return ((63 - p) << 6) + (63 - q);
        default: return (q << 6) + (63 - p);
    }
}

// ---------------------------------------------------------------------------
// FP32 GEMM with packed f32x2 FMA: C[M,N] = A[M,K] @ W[K,N] (+resid+bias)
// Tile 128x64, BK=16, 128 threads, 8x8 microtile, register-prefetch pipeline.
// ---------------------------------------------------------------------------
template<bool NG, bool RESID>
__global__ __launch_bounds__(128, 4)
void gemm_f2(const float* __restrict__ A, const float* __restrict__ W,
             float* __restrict__ C, int M, int N, int K,
             const float* __restrict__ resid, const float* __restrict__ bias)
{
    __shared__ __align__(16) float As[16][132];
    __shared__ __align__(16) float Bs[16][64];

    const int tid = threadIdx.x;
    const int tm = tid >> 3, tn = tid & 7;
    const int m0 = blockIdx.y * 128, n0 = blockIdx.x * 64;

    float4 rA[4], rB[2];

    auto loadA = [&](int k0) {
#pragma unroll
        for (int e = 0; e < 4; e++) {
            int l = e * 128 + tid; int r = l >> 2, kv = l & 3;
            rA[e] = *reinterpret_cast<const float4*>(&A[(size_t)(m0 + r) * K + k0 + kv * 4]);
        }
    };
    auto loadB = [&](int k0) {
#pragma unroll
        for (int e = 0; e < 2; e++) {
            int l = e * 128 + tid; int kk = l >> 4, c4 = l & 15;
            float4 w = make_float4(0.f, 0.f, 0.f, 0.f);
            if (!NG || (n0 + c4 * 4) < N)
                w = *reinterpret_cast<const float4*>(&W[(size_t)(k0 + kk) * N + n0 + c4 * 4]);
            rB[e] = w;
        }
    };
    auto stA = [&]() {
#pragma unroll
        for (int e = 0; e < 4; e++) {
            int l = e * 128 + tid; int r = l >> 2, kv = l & 3;
            As[kv * 4 + 0][r] = rA[e].x; As[kv * 4 + 1][r] = rA[e].y;
            As[kv * 4 + 2][r] = rA[e].z; As[kv * 4 + 3][r] = rA[e].w;
        }
    };
    auto stB = [&]() {
#pragma unroll
        for (int e = 0; e < 2; e++) {
            int l = e * 128 + tid; int kk = l >> 4, c4 = l & 15;
            *reinterpret_cast<float4*>(&Bs[kk][c4 * 4]) = rB[e];
        }
    };

    ull acc[8][4];
#pragma unroll
    for (int i = 0; i < 8; i++)
#pragma unroll
        for (int j = 0; j < 4; j++) acc[i][j] = 0ull;

    loadA(0); loadB(0);
    const int KT = K / 16;
    for (int kt = 0; kt < KT; kt++) {
        stA(); stB();
        __syncthreads();
        if (kt + 1 < KT) { loadA((kt + 1) * 16); loadB((kt + 1) * 16); }
#pragma unroll
        for (int kk = 0; kk < 16; kk++) {
            float4 a0 = *reinterpret_cast<const float4*>(&As[kk][tm * 8]);
            float4 a1 = *reinterpret_cast<const float4*>(&As[kk][tm * 8 + 4]);
            ull b[4];
#pragma unroll
            for (int j = 0; j < 4; j++)
                b[j] = *reinterpret_cast<const ull*>(&Bs[kk][tn * 8 + 2 * j]);
            float av[8] = {a0.x, a0.y, a0.z, a0.w, a1.x, a1.y, a1.z, a1.w};
#pragma unroll
            for (int i = 0; i < 8; i++) {
                ull ap = pk2(av[i], av[i]);
#pragma unroll
                for (int j = 0; j < 4; j++)
                    acc[i][j] = fma2(ap, b[j], acc[i][j]);
            }
        }
        __syncthreads();
    }

#pragma unroll
    for (int i = 0; i < 8; i++) {
        int r = m0 + tm * 8 + i;
#pragma unroll
        for (int j = 0; j < 4; j++) {
            int c = n0 + tn * 8 + 2 * j;
            if (NG && c >= N) continue;
            float lo, hi; upk(acc[i][j], lo, hi);
            size_t o = (size_t)r * N + c;
            if (RESID) { lo += resid[o] + bias[c]; hi += resid[o + 1] + bias[c + 1]; }
            float2 v = make_float2(lo, hi);
            *reinterpret_cast<float2*>(&C[o]) = v;
        }
    }
}

// ---------------------------------------------------------------------------
// Causal depthwise conv1d (4 taps) + SiLU: 8 timesteps/block, sliding window.
// ---------------------------------------------------------------------------
__global__ __launch_bounds__(384)
void conv_kernel(const float* __restrict__ conv_w, const float* __restrict__ conv_b)
{
    const int t0 = blockIdx.x * 8, n = blockIdx.y, d = threadIdx.x;
    const int dir = n >> 1, b = n & 1;
    const float w0 = conv_w[d * 4 + 0], w1 = conv_w[d * 4 + 1];
    const float w2 = conv_w[d * 4 + 2], w3 = conv_w[d * 4 + 3];
    const float bias = conv_b[d];

    float win0 = 0.f, win1 = 0.f, win2 = 0.f;
    if (t0 - 3 >= 0) win0 = g_P[((size_t)(b * LSEQ + gmap(dir, t0 - 3))) * 768 + d];
    if (t0 - 2 >= 0) win1 = g_P[((size_t)(b * LSEQ + gmap(dir, t0 - 2))) * 768 + d];
    if (t0 - 1 >= 0) win2 = g_P[((size_t)(b * LSEQ + gmap(dir, t0 - 1))) * 768 + d];

#pragma unroll
    for (int i = 0; i < 8; i++) {
        int t = t0 + i;
        float cur = g_P[((size_t)(b * LSEQ + gmap(dir, t))) * 768 + d];
        float acc = bias;
        acc = fmaf(w0, win0, acc);
        acc = fmaf(w1, win1, acc);
        acc = fmaf(w2, win2, acc);
        acc = fmaf(w3, cur,  acc);
        float s = acc / (1.f + __expf(-acc));
        g_xcs[((size_t)(n * LSEQ + t)) * DI + d] = s;
        win0 = win1; win1 = win2; win2 = cur;
    }
}

// Fast-path check: -A[d,s] == exp(A_log[d,s]) == s+1 for this problem.
__device__ __forceinline__ bool ladder_ok(const float* __restrict__ A_log, int d)
{
    bool ok = true;
#pragma unroll
    for (int s = 0; s < DS; s++) {
        float r = __expf(A_log[d * DS + s]);
        ok = ok && (fabsf(r - (float)(s + 1)) < 1e-3f);
    }
    return ok;
}

// Fused dt (serial form, used by scan1): a = bias + lr·Wc
__device__ __forceinline__ void dt_eval(const float* __restrict__ lr_t,
                                        const float* __restrict__ Wc, float bias,
                                        float& e1, float& dt)
{
    float a = bias;
#pragma unroll
    for (int k = 0; k < DTR; k++) a = fmaf(lr_t[k], Wc[k], a);
    float ea = __expf(a);
    float op = 1.f + ea;
    e1 = __fdividef(1.f, op);
    dt = __logf(op);
}

// Tree dot (used by scan3): 4 parallel partials
__device__ __forceinline__ float dt_dot(const float* __restrict__ lr_t,
                                        const float* __restrict__ Wc, float bias)
{
    float s0 = bias, s1 = 0.f, s2 = 0.f, s3 = 0.f;
#pragma unroll
    for (int k = 0; k < DTR; k += 4) {
        s0 = fmaf(lr_t[k],     Wc[k],     s0);
        s1 = fmaf(lr_t[k + 1], Wc[k + 1], s1);
        s2 = fmaf(lr_t[k + 2], Wc[k + 2], s2);
        s3 = fmaf(lr_t[k + 3], Wc[k + 3], s3);
    }
    return (s0 + s1) + (s2 + s3);
}

// ap tree (used by scan3): ap[j] = (e^{2j+1}, e^{2j+2}) via squaring
__device__ __forceinline__ void ap_tree(float e, ull ap[8])
{
    float e2 = e * e, e4 = e2 * e2, e8 = e4 * e4;
    ull E2 = pk2(e2, e2), E4 = pk2(e4, e4), E8 = pk2(e8, e8);
    ap[0] = pk2(e, e2);
    ap[1] = mul2(ap[0], E2);
    ap[2] = mul2(ap[0], E4);
    ap[3] = mul2(ap[1], E4);
    ap[4] = mul2(ap[0], E8);
    ap[5] = mul2(ap[1], E8);
    ap[6] = mul2(ap[2], E8);
    ap[7] = mul2(ap[3], E8);
}

// ---------------------------------------------------------------------------
// S1: within-chunk recurrence (h0=0) -> h_end + decay product E.
// SERIAL body — measured best for scan1 (56.0us, R15).
// ---------------------------------------------------------------------------
__global__ __launch_bounds__(384)
void scan1_kernel(const float* __restrict__ A_log,
                  const float* __restrict__ dt_proj_w, const float* __restrict__ dt_proj_b)
{
    const int g = blockIdx.x, n = blockIdx.y, d = threadIdx.x;
    __shared__ __align__(16) float Bs[CH_T][DS];
    __shared__ float lr[CH_T][DTR];
    const int base = n * LSEQ + g * CH_T;
    for (int i = threadIdx.x; i < CH_T * DS; i += 384) {
        int t = i >> 4, s = i & 15;
        Bs[t][s] = g_dbc[(size_t)(base + t) * 44 + DTR + s];
    }
    for (int i = threadIdx.x; i < CH_T * DTR; i += 384)
        lr[i / DTR][i % DTR] = g_dbc[(size_t)(base + i / DTR) * 44 + (i % DTR)];

    float Wc[DTR];
#pragma unroll
    for (int k = 0; k < DTR; k++) Wc[k] = dt_proj_w[k * DI + d];
    const float bias = dt_proj_b[d];
    __syncthreads();

    const bool fast = ladder_ok(A_log, d);
    float E = 1.f;
    const int cg = n * CH_G + g;

    if (fast) {
        ull h[8];
#pragma unroll
        for (int j = 0; j < 8; j++) h[j] = 0ull;
        for (int t = 0; t < CH_T; t++) {
            float e, dt;
            dt_eval(lr[t], Wc, bias, e, dt);
            float u = dt * g_xcs[(size_t)(base + t) * DI + d];
            E *= e;
            float e2 = e * e;
            ull e2p = pk2(e2, e2);
            ull up  = pk2(u, u);
            ull ap  = pk2(e, e2);
#pragma unroll
            for (int j = 0; j < 8; j++) {
                ull Bp = *reinterpret_cast<const ull*>(&Bs[t][2 * j]);
                h[j] = fma2(h[j], ap, mul2(up, Bp));
                if (j < 7) ap = mul2(ap, e2p);
            }
        }
#pragma unroll
        for (int j = 0; j < 8; j++) {
            float lo, hi; upk(h[j], lo, hi);
            g_hend[((size_t)(cg * DS + 2 * j))     * DI + d] = lo;
            g_hend[((size_t)(cg * DS + 2 * j + 1)) * DI + d] = hi;
        }
    } else {
        float h[DS];
#pragma unroll
        for (int s = 0; s < DS; s++) h[s] = 0.f;
        for (int t = 0; t < CH_T; t++) {
            float e, dtv;
            dt_eval(lr[t], Wc, bias, e, dtv);
            float u = dtv * g_xcs[(size_t)(base + t) * DI + d];
            E *= e;
#pragma unroll
            for (int s = 0; s < DS; s++) {
                float a = __expf(-dtv * __expf(A_log[d * DS + s]));
                h[s] = fmaf(h[s], a, u * Bs[t][s]);
            }
        }
#pragma unroll
        for (int s = 0; s < DS; s++)
            g_hend[((size_t)(cg * DS + s)) * DI + d] = h[s];
    }
    g_E[(size_t)cg * DI + d] = E;
}

// ---------------------------------------------------------------------------
// S2: serial scan over 64 chunk summaries per channel -> per-chunk h0
// ---------------------------------------------------------------------------
__global__ __launch_bounds__(384)
void scan2_kernel(const float* __restrict__ A_log)
{
    const int s = blockIdx.x, n = blockIdx.y, d = threadIdx.x;
    float r = __expf(A_log[d * DS + s]);
    const bool fast = fabsf(r - (float)(s + 1)) < 1e-3f;
    float h = 0.f;
    for (int g = 0; g < CH_G; g++) {
        int cg = n * CH_G + g;
        float E = g_E[(size_t)cg * DI + d];
        float a;
        if (fast) {
            a = 1.f; float p = E; int m = s + 1;
            while (m) { if (m & 1) a *= p; p *= p; m >>= 1; }
        } else {
            a = __powf(E, r);
        }
        size_t idx = ((size_t)(cg * DS + s)) * DI + d;
        g_h0[idx] = h;
        h = fmaf(a, h, g_hend[idx]);
    }
}

// ---------------------------------------------------------------------------
// S3: replay chunk from true h0, emit y (UN-permuted by gmap).
// TREE body + prefetch — measured best for scan3 (R8 vs R15 delta).
// ---------------------------------------------------------------------------
__global__ __launch_bounds__(384)
void scan3_kernel(const float* __restrict__ A_log, const float* __restrict__ Dv,
                  const float* __restrict__ dt_proj_w, const float* __restrict__ dt_proj_b)
{
    const int g = blockIdx.x, n = blockIdx.y, d = threadIdx.x;
    const int dir = n >> 1;
    __shared__ __align__(16) float Bs[CH_T][DS];
    __shared__ __align__(16) float Cs[CH_T][DS];
    __shared__ float lr[CH_T][DTR];
    const int base = n * LSEQ + g * CH_T;
    for (int i = threadIdx.x; i < CH_T * DS; i += 384) {
        int t = i >> 4, s = i & 15;
        size_t ro = (size_t)(base + t) * 44;
        Bs[t][s] = g_dbc[ro + DTR + s];
        Cs[t][s] = g_dbc[ro + DTR + DS + s];
    }
    for (int i = threadIdx.x; i < CH_T * DTR; i += 384)
        lr[i / DTR][i % DTR] = g_dbc[(size_t)(base + i / DTR) * 44 + (i % DTR)];

    float Wc[DTR];
#pragma unroll
    for (int k = 0; k < DTR; k++) Wc[k] = dt_proj_w[k * DI + d];
    const float bias = dt_proj_b[d];
    __syncthreads();

    const bool fast = ladder_ok(A_log, d);
    const int cg = n * CH_G + g;
    const float Dd = Dv[d];

    if (fast) {
        ull h[8];
#pragma unroll
        for (int j = 0; j < 8; j++)
            h[j] = pk2(g_h0[((size_t)(cg * DS + 2 * j))     * DI + d],
                       g_h0[((size_t)(cg * DS + 2 * j + 1)) * DI + d]);
        float xc_n = g_xcs[(size_t)base * DI + d];
        float a_n  = dt_dot(lr[0], Wc, bias);
        for (int t = 0; t < CH_T; t++) {
            float a = a_n, xc = xc_n;
            if (t + 1 < CH_T) {
                xc_n = g_xcs[(size_t)(base + t + 1) * DI + d];
                a_n  = dt_dot(lr[t + 1], Wc, bias);
            }
            float ea = __expf(a), op = 1.f + ea;
            float e  = __fdividef(1.f, op);
            float u  = __logf(op) * xc;
            ull ap[8]; ap_tree(e, ap);
            ull up = pk2(u, u);
            ull y2 = 0ull;
#pragma unroll
            for (int j = 0; j < 8; j++) {
                ull Bp = *reinterpret_cast<const ull*>(&Bs[t][2 * j]);
                ull Cp = *reinterpret_cast<const ull*>(&Cs[t][2 * j]);
                h[j] = fma2(h[j], ap[j], mul2(up, Bp));
                y2   = fma2(h[j], Cp, y2);
            }
            float ylo, yhi; upk(y2, ylo, yhi);
            float y = ylo + yhi;
            y = fmaf(xc, Dd, y);
            int u_tok = gmap(dir, g * CH_T + t);
            g_y[((size_t)(n * LSEQ + u_tok)) * DI + d] = y;
        }
    } else {
        float h[DS];
#pragma unroll
        for (int s = 0; s < DS; s++)
            h[s] = g_h0[((size_t)(cg * DS + s)) * DI + d];
        for (int t = 0; t < CH_T; t++) {
            size_t idx = (size_t)(base + t) * DI + d;
            float a = dt_dot(lr[t], Wc, bias);
            float ea = __expf(a), op = 1.f + ea;
            float e  = __fdividef(1.f, op);
            float dtv = __logf(op);
            float xc = g_xcs[idx];
            float u = dtv * xc;
            float y = 0.f;
#pragma unroll
            for (int s = 0; s < DS; s++) {
                float aa = __expf(-dtv * __expf(A_log[d * DS + s]));
                h[s] = fmaf(h[s], aa, u * Bs[t][s]);
                y = fmaf(h[s], Cs[t][s], y);
            }
            y = fmaf(xc, Dd, y);
            int u_tok = gmap(dir, g * CH_T + t);
            g_y[((size_t)(n * LSEQ + u_tok)) * DI + d] = y;
        }
    }
}

// ---------------------------------------------------------------------------
// Sum the 4 (already un-permuted) directional y's, multiply by silu(z).
// ---------------------------------------------------------------------------
__global__ __launch_bounds__(384)
void gather_kernel()
{
    const int u = blockIdx.x, d = threadIdx.x;
    const int b = u >> 12, to = u & 4095;
    float ys = g_y[((size_t)((0 + b) * LSEQ + to)) * DI + d]
             + g_y[((size_t)((2 + b) * LSEQ + to)) * DI + d]
             + g_y[((size_t)((4 + b) * LSEQ + to)) * DI + d]
             + g_y[((size_t)((6 + b) * LSEQ + to)) * DI + d];
    float z  = g_P[((size_t)(b * LSEQ + to)) * 768 + DI + d];
    float sz = z / (1.f + __expf(-z));
    g_G[((size_t)u) * DI + d] = ys * sz;
}

// ---------------------------------------------------------------------------
// LayerNorm over 192 channels
// ---------------------------------------------------------------------------
__global__ __launch_bounds__(192)
void ln_kernel(const float* __restrict__ lg, const float* __restrict__ lb)
{
    const int u = blockIdx.x, j = threadIdx.x;
    float v = g_O1[(size_t)u * DM + j];
    __shared__ float rs[6], rq[6], stats[2];
    float s1 = v, s2 = v * v;
#pragma unroll
    for (int o = 16; o > 0; o >>= 1) {
        s1 += __shfl_down_sync(0xffffffffu, s1, o);
        s2 += __shfl_down_sync(0xffffffffu, s2, o);
    }
    if ((j & 31) == 0) { rs[j >> 5] = s1; rq[j >> 5] = s2; }
    __syncthreads();
    if (j == 0) {
        float a = 0.f, q = 0.f;
        for (int i = 0; i < 6; i++) { a += rs[i]; q += rq[i]; }
        float mu = a * (1.f / DM);
        float var = q * (1.f / DM) - mu * mu;
        stats[0] = mu; stats[1] = rsqrtf(var + 1e-5f);
    }
    __syncthreads();
    g_N1[(size_t)u * DM + j] = (v - stats[0]) * stats[1] * lg[j] + lb[j];
}

// ---------------------------------------------------------------------------
// Launch
// ---------------------------------------------------------------------------
extern "C" void kernel_launch(void* const* d_in, const int* in_sizes, int n_in,
                              void* d_out, int out_size)
{
    const float* x           = (const float*)d_in[0];
    const float* in_proj_w   = (const float*)d_in[1];
    const float* conv_w      = (const float*)d_in[2];
    const float* conv_b      = (const float*)d_in[3];
    const float* x_proj_w    = (const float*)d_in[4];
    const float* dt_proj_w   = (const float*)d_in[5];
    const float* dt_proj_b   = (const float*)d_in[6];
    const float* A_log       = (const float*)d_in[7];
    const float* Dv          = (const float*)d_in[8];
    const float* mamba_out_w = (const float*)d_in[9];
    const float* ln_g        = (const float*)d_in[10];
    const float* ln_b        = (const float*)d_in[11];
    const float* blk_w       = (const float*)d_in[12];
    const float* blk_b       = (const float*)d_in[13];
    float* out = (float*)d_out;

    float *P, *xcs, *dbc, *G, *O1, *N1;
    cudaGetSymbolAddress((void**)&P,   g_P);
    cudaGetSymbolAddress((void**)&xcs, g_xcs);
    cudaGetSymbolAddress((void**)&dbc, g_dbc);
    cudaGetSymbolAddress((void**)&G,   g_G);
    cudaGetSymbolAddress((void**)&O1,  g_O1);
    cudaGetSymbolAddress((void**)&N1,  g_N1);

    // 1) P = x @ in_proj_w              [8192,192]x[192,768]
    gemm_f2<false, false><<<dim3(12, 64), 128>>>(x, in_proj_w, P,
                                                 NTOK, 768, DM, nullptr, nullptr);
    // 2) depthwise conv + SiLU (8 t/block, sliding window)
    conv_kernel<<<dim3(LSEQ / 8, NSEQ), 384>>>(conv_w, conv_b);
    // 3) dbc = xcs @ x_proj_w           [32768,384]x[384,44]
    gemm_f2<true, false><<<dim3(1, 256), 128>>>(xcs, x_proj_w, dbc,
                                                NROWS, 44, DI, nullptr, nullptr);
    // 4-6) chunked selective scan (scan1 serial body, scan3 tree body)
    scan1_kernel<<<dim3(CH_G, NSEQ), 384>>>(A_log, dt_proj_w, dt_proj_b);
    scan2_kernel<<<dim3(DS, NSEQ), 384>>>(A_log);
    scan3_kernel<<<dim3(CH_G, NSEQ), 384>>>(A_log, Dv, dt_proj_w, dt_proj_b);
    // 7) direction merge * silu(z)
    gather_kernel<<<NTOK, 384>>>();
    // 8) O1 = G @ mamba_out_w           [8192,384]x[384,192]
    gemm_f2<false, false><<<dim3(3, 64), 128>>>(G, mamba_out_w, O1,
                                                NTOK, DM, DI, nullptr, nullptr);
    // 9) LayerNorm
    ln_kernel<<<NTOK, DM>>>(ln_g, ln_b);
    // 10) out = x + N1 @ blk_w + blk_b
    gemm_f2<false, true><<<dim3(3, 64), 128>>>(N1, blk_w, out,
                                               NTOK, DM, DM, x, blk_b);
    (void)in_sizes; (void)n_in; (void)out_size;
}